// round 12
// baseline (speedup 1.0000x reference)
#include <cuda_runtime.h>
#include <cuda_fp16.h>
#include <cstdint>

#define DEV __device__ __forceinline__

#if defined(__CUDA_ARCH_FEAT_SM103_ALL) || defined(__CUDA_ARCH_FAMILY_SPECIFIC__) || \
    (defined(__CUDA_ARCH_SPECIFIC__) && (__CUDA_ARCH_SPECIFIC__ == 1030))
#define HAS_TC 1
#else
#define HAS_TC 0
#endif

static constexpr int B_DIM = 4096, D_IN = 256, D_OUT = 256, KBAS = 64;
static constexpr int KSPLIT = 4, I_PER = D_IN / KSPLIT;   // 64 i per CTA
static constexpr int MT = 128, NT = 256;
static constexpr int STAGES = 6;          // 1 i per stage (K=64), deep pipeline
static constexpr int ITERS = I_PER;       // 64
static constexpr int CLUS = 4;

static constexpr uint32_t MMA_IDESC = (1u << 4) | ((NT / 8) << 17) | ((MT / 16) << 24);
static constexpr uint64_t DESC_BASE =
    (uint64_t(2) << 61) | (uint64_t(1) << 46) | (uint64_t(64) << 32) | (uint64_t(1) << 16);

__device__ __half g_Cs[(size_t)D_IN * D_OUT * KBAS];          // SW128 fp16 B tiles
__device__ uint4  g_W[(size_t)B_DIM * D_IN];                  // packed A-row records {v0,v1,v2,basecol}
__device__ float  g_partial[(size_t)KSPLIT * B_DIM * D_OUT];  // 16 MB

// smem: barriers + B stages only (A lives in TMEM)
static constexpr int SM_TMEM = 0, SM_FULL = 16, SM_ADONE = 64, SM_BDONE = 112, SM_FINAL = 160;
static constexpr int B_ST = NT * KBAS * 2;                     // 32768
static constexpr int SM_B = 1024;
static constexpr int SMEM_TC = SM_B + STAGES * B_ST;           // 197632
// TMEM: D at cols [0,256); A stage st at cols 256 + st*32
static constexpr int TMEM_A0 = 256;

DEV uint32_t smem_u32(const void* p) {
    uint32_t a;
    asm("{ .reg .u64 t; cvta.to.shared.u64 t, %1; cvt.u32.u64 %0, t; }" : "=r"(a) : "l"(p));
    return a;
}
DEV uint32_t elect_one() {
    uint32_t r;
    asm volatile("{ .reg .pred p; elect.sync _|p, 0xFFFFFFFF; selp.b32 %0,1,0,p; }" : "=r"(r));
    return r;
}
DEV void mbar_init(uint32_t m, uint32_t c) {
    asm volatile("mbarrier.init.shared.b64 [%0], %1;" :: "r"(m), "r"(c) : "memory");
}
DEV void mbar_arrive(uint32_t m) {
    asm volatile("mbarrier.arrive.release.cta.shared::cta.b64 _, [%0];" :: "r"(m) : "memory");
}
DEV void mbar_expect_tx(uint32_t m, uint32_t b) {
    asm volatile("mbarrier.arrive.expect_tx.shared.b64 _, [%0], %1;" :: "r"(m), "r"(b) : "memory");
}
DEV void mbar_wait(uint32_t m, uint32_t ph) {   // acquire
    uint32_t done;
    asm volatile("{ .reg .pred p; mbarrier.try_wait.parity.acquire.cta.shared::cta.b64 p, [%1], %2;"
                 " selp.b32 %0,1,0,p; }" : "=r"(done) : "r"(m), "r"(ph) : "memory");
    while (!done)
        asm volatile("{ .reg .pred p; mbarrier.try_wait.parity.acquire.cta.shared::cta.b64 p, [%1], %2, 0x989680;"
                     " selp.b32 %0,1,0,p; }" : "=r"(done) : "r"(m), "r"(ph) : "memory");
}
DEV void mbar_wait_rlx(uint32_t m, uint32_t ph) {
    uint32_t done;
    asm volatile("{ .reg .pred p; mbarrier.try_wait.parity.relaxed.cta.shared::cta.b64 p, [%1], %2, 0x989680;"
                 " selp.b32 %0,1,0,p; }" : "=r"(done) : "r"(m), "r"(ph) : "memory");
    while (!done)
        asm volatile("{ .reg .pred p; mbarrier.try_wait.parity.relaxed.cta.shared::cta.b64 p, [%1], %2, 0x989680;"
                     " selp.b32 %0,1,0,p; }" : "=r"(done) : "r"(m), "r"(ph) : "memory");
}
DEV void tc_fence_before() { asm volatile("tcgen05.fence::before_thread_sync;" ::: "memory"); }
DEV void tc_fence_after()  { asm volatile("tcgen05.fence::after_thread_sync;" ::: "memory"); }
DEV void tc_wait_st() { asm volatile("tcgen05.wait::st.sync.aligned;" ::: "memory"); }

// exact Cox-de Boor p=3 on analytic uniform knots: t[k] = fma(k, 8/67, -4)
DEV bool basis4a(float u, float Nv[4], int& k0) {
    if (!(u >= -4.0f && u < 4.0f)) return false;
    const float h  = 8.0f / 67.0f;
    const float i1 = 8.375f;
    const float i2 = 0.5f * i1;
    const float i3 = (1.0f / 3.0f) * i1;
    int s_ = (int)((u + 4.0f) * i1);
    s_ = min(max(s_, 0), 66);
    if (u < fmaf((float)s_, h, -4.0f)) s_--;
    else if (u >= fmaf((float)(s_ + 1), h, -4.0f)) s_++;
    s_ = min(max(s_, 0), 66);
    k0 = min(max(s_ - 3, 0), 60);
    float tk[8];
    #pragma unroll
    for (int j = 0; j < 8; j++) tk[j] = fmaf((float)(k0 + j), h, -4.0f);
    float N[7];
    #pragma unroll
    for (int j = 0; j < 7; j++) N[j] = (k0 + j == s_) ? 1.0f : 0.0f;
    #pragma unroll
    for (int j = 0; j < 6; j++)
        N[j] = (u - tk[j]) * i1 * N[j] + (tk[j + 2] - u) * i1 * N[j + 1];
    #pragma unroll
    for (int j = 0; j < 5; j++)
        N[j] = (u - tk[j]) * i2 * N[j] + (tk[j + 3] - u) * i2 * N[j + 1];
    #pragma unroll
    for (int j = 0; j < 4; j++)
        Nv[j] = (u - tk[j]) * i3 * N[j] + (tk[j + 4] - u) * i3 * N[j + 1];
    return true;
}

// fused prep: blocks [0,2048) coeffs*mask -> g_Cs; blocks [2048,6144) packed A records
__global__ void __launch_bounds__(256) kan_prep(const float* __restrict__ coeffs,
                                                const float* __restrict__ mask,
                                                const float* __restrict__ x) {
    if (blockIdx.x < 2048) {
        uint32_t idx = blockIdx.x * 256u + threadIdx.x;
        uint32_t i = idx >> 11, o = (idx >> 3) & 255u, kg = idx & 7u;
        float mv = __ldg(mask + o * 256u + i);
        const float4* cp = reinterpret_cast<const float4*>(coeffs + ((size_t)(o * 256u + i)) * 64u + kg * 8u);
        float4 c0 = __ldg(cp), c1 = __ldg(cp + 1);
        __half2 t0 = __floats2half2_rn(c0.x * mv, c0.y * mv), t1 = __floats2half2_rn(c0.z * mv, c0.w * mv);
        __half2 t2 = __floats2half2_rn(c1.x * mv, c1.y * mv), t3 = __floats2half2_rn(c1.z * mv, c1.w * mv);
        uint32_t bo = o * 128u + kg * 16u, sw = bo ^ ((bo >> 3) & 0x70u);
        uint4 v;
        v.x = *reinterpret_cast<uint32_t*>(&t0);
        v.y = *reinterpret_cast<uint32_t*>(&t1);
        v.z = *reinterpret_cast<uint32_t*>(&t2);
        v.w = *reinterpret_cast<uint32_t*>(&t3);
        *reinterpret_cast<uint4*>(reinterpret_cast<char*>(g_Cs) + (size_t)i * 32768u + sw) = v;
    } else {
        int b = blockIdx.x - 2048, i = threadIdx.x;
        float u = __ldg(x + (size_t)b * D_IN + i);
        float Nv[4]; int k0 = 0;
        uint4 rec = {0u, 0u, 0u, 0u};
        if (basis4a(u, Nv, k0)) {
            // pack 4 fp16 weights at half-position k0 into 3 b32 cols at base col bc
            int bc = min(k0 >> 1, 29);
            int lo = k0 - 2 * bc;          // 0,1,2
            uint32_t hb[4];
            #pragma unroll
            for (int j = 0; j < 4; j++)
                hb[j] = (uint32_t)__half_as_ushort(__float2half_rn(Nv[j]));
            uint32_t hh[6] = {0, 0, 0, 0, 0, 0};
            #pragma unroll
            for (int j = 0; j < 4; j++) hh[lo + j] = hb[j];
            rec.x = hh[0] | (hh[1] << 16);
            rec.y = hh[2] | (hh[3] << 16);
            rec.z = hh[4] | (hh[5] << 16);
            rec.w = (uint32_t)bc;
        }
        g_W[(size_t)b * D_IN + i] = rec;
    }
}

// tcgen05 GEMM: TS mode (A in TMEM), K=64/stage, 6 stages, cluster-of-4 B multicast
__global__ void __launch_bounds__(192, 1) __cluster_dims__(CLUS, 1, 1)
kan_gemm_tc(const float* __restrict__ x) {
#if HAS_TC
    extern __shared__ char smem[];
    uint32_t sb = smem_u32(smem);
    int tid = threadIdx.x, wid = tid >> 5;
    int m = blockIdx.x & 31, kc = blockIdx.x >> 5;
    uint32_t rank;
    asm("mov.u32 %0, %%cluster_ctarank;" : "=r"(rank));

    if (tid == 0) {
        #pragma unroll
        for (int s = 0; s < STAGES; s++) {
            mbar_init(sb + SM_FULL + 8 * s, 5);     // 4 producer-warp arrives + expect_tx
            mbar_init(sb + SM_ADONE + 8 * s, 1);    // local MMA commit (A slot reuse)
            mbar_init(sb + SM_BDONE + 8 * s, CLUS); // 4 multicast commits (B slot reuse)
        }
        mbar_init(sb + SM_FINAL, 1);
    }
    if (wid == 5) {
        asm volatile("tcgen05.alloc.cta_group::1.sync.aligned.shared::cta.b32 [%0], %1;"
                     :: "r"(sb + SM_TMEM), "r"(512u) : "memory");
        asm volatile("tcgen05.relinquish_alloc_permit.cta_group::1.sync.aligned;");
    }
    __syncthreads();
    asm volatile("barrier.cluster.arrive.aligned;" ::: "memory");
    asm volatile("barrier.cluster.wait.aligned;" ::: "memory");

    uint32_t tmem;
    asm volatile("ld.shared.b32 %0, [%1];" : "=r"(tmem) : "r"(sb + SM_TMEM));

    if (tid < 128) {
        // ---- A producer: build dense 64-half row in regs, one STTM x32 per stage ----
        const uint4* recs = g_W + ((size_t)(m * MT + tid)) * D_IN + kc * I_PER;
        uint32_t warp_off = ((uint32_t)tid >> 5) << 21;
        uint4 rn = recs[0];
        int st = 0, q = 0;
        for (int it = 0; it < ITERS; it++) {
            uint4 r = rn;
            if (it + 1 < ITERS) rn = recs[it + 1];
            mbar_wait(sb + SM_ADONE + 8 * st, (uint32_t)((q - 1) & 1));
            tc_fence_after();
            uint32_t a[32];
            int bc = (int)r.w;
            #pragma unroll
            for (int j = 0; j < 32; j++) {
                int t = j - bc;
                a[j] = (t == 0) ? r.x : (t == 1) ? r.y : (t == 2) ? r.z : 0u;
            }
            uint32_t adst = tmem + TMEM_A0 + (uint32_t)st * 32u + warp_off;
            asm volatile(
                "tcgen05.st.sync.aligned.32x32b.x32.b32 [%0], "
                "{%1,%2,%3,%4,%5,%6,%7,%8,%9,%10,%11,%12,%13,%14,%15,%16,"
                "%17,%18,%19,%20,%21,%22,%23,%24,%25,%26,%27,%28,%29,%30,%31,%32};"
                :: "r"(adst),
                   "r"(a[0]),  "r"(a[1]),  "r"(a[2]),  "r"(a[3]),
                   "r"(a[4]),  "r"(a[5]),  "r"(a[6]),  "r"(a[7]),
                   "r"(a[8]),  "r"(a[9]),  "r"(a[10]), "r"(a[11]),
                   "r"(a[12]), "r"(a[13]), "r"(a[14]), "r"(a[15]),
                   "r"(a[16]), "r"(a[17]), "r"(a[18]), "r"(a[19]),
                   "r"(a[20]), "r"(a[21]), "r"(a[22]), "r"(a[23]),
                   "r"(a[24]), "r"(a[25]), "r"(a[26]), "r"(a[27]),
                   "r"(a[28]), "r"(a[29]), "r"(a[30]), "r"(a[31])
                : "memory");
            tc_wait_st();
            tc_fence_before();
            __syncwarp();
            if (elect_one()) mbar_arrive(sb + SM_FULL + 8 * st);
            if (++st == STAGES) { st = 0; q++; }
        }
    } else if (tid == 128) {
        // ---- B producer: multicast 8KB slice of 32KB stage to 4-CTA cluster ----
        const char* src0 = reinterpret_cast<const char*>(g_Cs) +
                           (size_t)(kc * I_PER) * 32768u + rank * 8192u;
        int st = 0, q = 0;
        for (int it = 0; it < ITERS; it++) {
            mbar_wait_rlx(sb + SM_BDONE + 8 * st, (uint32_t)((q - 1) & 1));
            mbar_expect_tx(sb + SM_FULL + 8 * st, B_ST);
            asm volatile(
                "cp.async.bulk.shared::cluster.global.mbarrier::complete_tx::bytes.multicast::cluster"
                " [%0], [%1], %2, [%3], %4;"
                :: "r"(sb + SM_B + st * B_ST + rank * 8192u),
                   "l"(src0 + (size_t)it * 32768u),
                   "r"(8192u), "r"(sb + SM_FULL + 8 * st), "h"((uint16_t)0xF) : "memory");
            if (++st == STAGES) { st = 0; q++; }
        }
    } else if (wid == 5) {
        // ---- MMA warp: TS dispatches (A in TMEM) ----
        int st = 0, q = 0;
        for (int it = 0; it < ITERS; it++) {
            mbar_wait(sb + SM_FULL + 8 * st, (uint32_t)(q & 1));
            tc_fence_after();
            if (elect_one()) {
                uint64_t db = DESC_BASE | (((uint64_t)((sb + SM_B + st * B_ST) >> 4)) & 0x3FFF);
                uint32_t at = tmem + TMEM_A0 + (uint32_t)st * 32u;
                #pragma unroll
                for (int ks = 0; ks < 4; ks++) {
                    uint32_t en = (it == 0 && ks == 0) ? 0u : 1u;
                    asm volatile(
                        "{ .reg .pred p; setp.ne.u32 p, %4, 0;"
                        " tcgen05.mma.cta_group::1.kind::f16 [%0], [%1], %2, %3, {%5,%5,%5,%5}, p; }"
                        :: "r"(tmem), "r"(at + ks * 8), "l"(db + 2 * ks),
                           "r"(MMA_IDESC), "r"(en), "r"(0u) : "memory");
                }
                asm volatile("tcgen05.commit.cta_group::1.mbarrier::arrive::one.shared::cluster.b64 [%0];"
                             :: "r"(sb + SM_ADONE + 8 * st) : "memory");
                asm volatile(
                    "tcgen05.commit.cta_group::1.mbarrier::arrive::one.shared::cluster.multicast::cluster.b64"
                    " [%0], %1;" :: "r"(sb + SM_BDONE + 8 * st), "h"((uint16_t)0xF) : "memory");
            }
            if (++st == STAGES) { st = 0; q++; }
        }
        if (elect_one())
            asm volatile("tcgen05.commit.cta_group::1.mbarrier::arrive::one.shared::cluster.b64 [%0];"
                         :: "r"(sb + SM_FINAL) : "memory");
    }
    __syncthreads();

    if (tid < 128) {
        mbar_wait(sb + SM_FINAL, 0);
        tc_fence_after();
        float* dst = g_partial + (size_t)kc * (B_DIM * D_OUT) + (size_t)(m * MT + tid) * D_OUT;
        #pragma unroll
        for (int c = 0; c < NT; c += 32) {
            uint32_t r[32];
            asm volatile(
                "tcgen05.ld.sync.aligned.32x32b.x32.b32 "
                "{%0,%1,%2,%3,%4,%5,%6,%7,%8,%9,%10,%11,%12,%13,%14,%15,"
                "%16,%17,%18,%19,%20,%21,%22,%23,%24,%25,%26,%27,%28,%29,%30,%31}, [%32];"
                : "=r"(r[0]), "=r"(r[1]), "=r"(r[2]), "=r"(r[3]), "=r"(r[4]), "=r"(r[5]),
                  "=r"(r[6]), "=r"(r[7]), "=r"(r[8]), "=r"(r[9]), "=r"(r[10]), "=r"(r[11]),
                  "=r"(r[12]), "=r"(r[13]), "=r"(r[14]), "=r"(r[15]), "=r"(r[16]), "=r"(r[17]),
                  "=r"(r[18]), "=r"(r[19]), "=r"(r[20]), "=r"(r[21]), "=r"(r[22]), "=r"(r[23]),
                  "=r"(r[24]), "=r"(r[25]), "=r"(r[26]), "=r"(r[27]), "=r"(r[28]), "=r"(r[29]),
                  "=r"(r[30]), "=r"(r[31])
                : "r"(tmem + c));
            asm volatile("tcgen05.wait::ld.sync.aligned;" ::: "memory");
            #pragma unroll
            for (int j = 0; j < 32; j += 4) {
                float4 v;
                v.x = __uint_as_float(r[j]); v.y = __uint_as_float(r[j + 1]);
                v.z = __uint_as_float(r[j + 2]); v.w = __uint_as_float(r[j + 3]);
                *reinterpret_cast<float4*>(dst + c + j) = v;
            }
        }
    }
    __syncthreads();
    if (wid == 5)
        asm volatile("tcgen05.dealloc.cta_group::1.sync.aligned.b32 %0, %1;" :: "r"(tmem), "r"(512u));
    asm volatile("barrier.cluster.arrive.aligned;" ::: "memory");
    asm volatile("barrier.cluster.wait.aligned;" ::: "memory");
#else
    (void)x;
#endif
}

__global__ void __launch_bounds__(256) kan_reduce(float* __restrict__ out) {
    uint32_t idx = blockIdx.x * 256u + threadIdx.x;
    const float4* p = reinterpret_cast<const float4*>(g_partial);
    float4 a = p[idx], b = p[idx + 262144u], c = p[idx + 524288u], d = p[idx + 786432u];
    float4 r;
    r.x = a.x + b.x + c.x + d.x; r.y = a.y + b.y + c.y + d.y;
    r.z = a.z + b.z + c.z + d.z; r.w = a.w + b.w + c.w + d.w;
    reinterpret_cast<float4*>(out)[idx] = r;
}

extern "C" void kernel_launch(void* const* d_in, const int* in_sizes, int n_in,
                              void* d_out, int out_size) {
    const float* x = (const float*)d_in[0];
    const float* coeffs = (const float*)d_in[1];
    const float* mask = (const float*)d_in[2];
    float* out = (float*)d_out;
    (void)in_sizes; (void)n_in; (void)out_size;

    cudaFuncSetAttribute(kan_gemm_tc, cudaFuncAttributeMaxDynamicSharedMemorySize, SMEM_TC);

    kan_prep<<<6144, 256>>>(coeffs, mask, x);
    kan_gemm_tc<<<KSPLIT * 32, 192, SMEM_TC>>>(x);
    kan_reduce<<<1024, 256>>>(out);
}

// round 13
// speedup vs baseline: 3.1928x; 3.1928x over previous
#include <cuda_runtime.h>
#include <cuda_fp16.h>
#include <cstdint>

#define DEV __device__ __forceinline__

#if defined(__CUDA_ARCH_FEAT_SM103_ALL) || defined(__CUDA_ARCH_FAMILY_SPECIFIC__) || \
    (defined(__CUDA_ARCH_SPECIFIC__) && (__CUDA_ARCH_SPECIFIC__ == 1030))
#define HAS_TC 1
#else
#define HAS_TC 0
#endif

static constexpr int B_DIM = 4096, D_IN = 256, D_OUT = 256, KBAS = 64;
static constexpr int KSPLIT = 8, I_PER = D_IN / KSPLIT;   // 32 i per CTA
static constexpr int MT = 128, NT = 256;
static constexpr int STAGES = 3;          // 1 i per stage; A holds both M-subtiles
static constexpr int ITERS = I_PER;       // 32

static constexpr uint32_t MMA_IDESC = (1u << 4) | ((NT / 8) << 17) | ((MT / 16) << 24);
static constexpr uint64_t DESC_BASE =
    (uint64_t(2) << 61) | (uint64_t(1) << 46) | (uint64_t(64) << 32) | (uint64_t(1) << 16);

__device__ __half g_Cs[(size_t)D_IN * D_OUT * KBAS];          // SW128 fp16 B tiles
__device__ uint4  g_W[(size_t)B_DIM * D_IN];                  // basis records [b][i]
__device__ float  g_partial[(size_t)KSPLIT * B_DIM * D_OUT];  // 32 MB

// tc smem layout (all barriers CTA-local)
static constexpr int SM_TMEM = 0, SM_FULL = 16, SM_DONE = 48, SM_FINAL = 80;
static constexpr int A_ST = 2 * MT * KBAS * 2;                 // 32768 (two M=128 subtiles)
static constexpr int B_ST = NT * KBAS * 2;                     // 32768
static constexpr int SM_A = 1024;
static constexpr int SM_B = SM_A + STAGES * A_ST;              // 99328
static constexpr int SMEM_TC = SM_B + STAGES * B_ST;           // 197632

DEV uint32_t smem_u32(const void* p) {
    uint32_t a;
    asm("{ .reg .u64 t; cvta.to.shared.u64 t, %1; cvt.u32.u64 %0, t; }" : "=r"(a) : "l"(p));
    return a;
}
DEV uint32_t elect_one() {
    uint32_t r;
    asm volatile("{ .reg .pred p; elect.sync _|p, 0xFFFFFFFF; selp.b32 %0,1,0,p; }" : "=r"(r));
    return r;
}
DEV void mbar_init(uint32_t m, uint32_t c) {
    asm volatile("mbarrier.init.shared.b64 [%0], %1;" :: "r"(m), "r"(c) : "memory");
}
DEV void mbar_arrive(uint32_t m) {
    asm volatile("mbarrier.arrive.release.cta.shared::cta.b64 _, [%0];" :: "r"(m) : "memory");
}
DEV void mbar_expect_tx(uint32_t m, uint32_t b) {
    asm volatile("mbarrier.arrive.expect_tx.shared.b64 _, [%0], %1;" :: "r"(m), "r"(b) : "memory");
}
DEV void mbar_wait(uint32_t m, uint32_t ph) {   // acquire
    uint32_t done;
    asm volatile("{ .reg .pred p; mbarrier.try_wait.parity.acquire.cta.shared::cta.b64 p, [%1], %2;"
                 " selp.b32 %0,1,0,p; }" : "=r"(done) : "r"(m), "r"(ph) : "memory");
    while (!done)
        asm volatile("{ .reg .pred p; mbarrier.try_wait.parity.acquire.cta.shared::cta.b64 p, [%1], %2, 0x989680;"
                     " selp.b32 %0,1,0,p; }" : "=r"(done) : "r"(m), "r"(ph) : "memory");
}
DEV void mbar_wait_rlx(uint32_t m, uint32_t ph) {   // post-wait accesses async-proxy only
    uint32_t done;
    asm volatile("{ .reg .pred p; mbarrier.try_wait.parity.relaxed.cta.shared::cta.b64 p, [%1], %2, 0x989680;"
                 " selp.b32 %0,1,0,p; }" : "=r"(done) : "r"(m), "r"(ph) : "memory");
    while (!done)
        asm volatile("{ .reg .pred p; mbarrier.try_wait.parity.relaxed.cta.shared::cta.b64 p, [%1], %2, 0x989680;"
                     " selp.b32 %0,1,0,p; }" : "=r"(done) : "r"(m), "r"(ph) : "memory");
}
DEV void fence_async_shared() { asm volatile("fence.proxy.async.shared::cta;" ::: "memory"); }
DEV void sts128_zero(uint32_t a) {
    asm volatile("st.shared.v4.b32 [%0], {%1,%1,%1,%1};" :: "r"(a), "r"(0u) : "memory");
}
DEV void sts_u16(uint32_t a, uint16_t v) {
    asm volatile("st.shared.u16 [%0], %1;" :: "r"(a), "h"(v) : "memory");
}

// exact basis via cardinal cubic polynomials on uniform knots (== Cox-de Boor here).
// span s from analytic knots t[k]=fma(k,8/67,-4); k0 = clamp(s-3,0,60);
// Nv[j] = Q_{s-k0-j}(r), r=(u-t_s)*67/8, Q out-of-range -> 0 (matches clamped-window refs).
DEV bool basis4c(float u, float Nv[4], int& k0) {
    if (!(u >= -4.0f && u < 4.0f)) return false;
    const float h = 8.0f / 67.0f, i1 = 8.375f;
    int s = (int)((u + 4.0f) * i1);
    s = min(max(s, 0), 66);
    float ts = fmaf((float)s, h, -4.0f);
    if (u < ts) s--;
    else if (u >= ts + h) s++;
    s = min(max(s, 0), 66);
    ts = fmaf((float)s, h, -4.0f);
    k0 = min(max(s - 3, 0), 60);
    float r = (u - ts) * i1;
    float r2 = r * r, r3 = r2 * r;
    float q0 = r3 * (1.0f / 6.0f);
    float q1 = fmaf(-3.0f, r3, fmaf(3.0f, r2, fmaf(3.0f, r, 1.0f))) * (1.0f / 6.0f);
    float q2 = fmaf(3.0f, r3, fmaf(-6.0f, r2, 4.0f)) * (1.0f / 6.0f);
    float omr = 1.0f - r;
    float q3 = omr * omr * omr * (1.0f / 6.0f);
    int dd = s - k0;   // 3 interior; 0..2 low edge; 4..6 high edge
    #pragma unroll
    for (int j = 0; j < 4; j++) {
        int d = dd - j;
        Nv[j] = (d == 0) ? q0 : (d == 1) ? q1 : (d == 2) ? q2 : (d == 3) ? q3 : 0.0f;
    }
    return true;
}

// fused prep: blocks [0,2048) convert coeffs*mask -> g_Cs; blocks [2048,6144) basis records
__global__ void __launch_bounds__(256) kan_prep(const float* __restrict__ coeffs,
                                                const float* __restrict__ mask,
                                                const float* __restrict__ x) {
    if (blockIdx.x < 2048) {
        uint32_t idx = blockIdx.x * 256u + threadIdx.x;
        uint32_t i = idx >> 11, o = (idx >> 3) & 255u, kg = idx & 7u;
        float mv = __ldg(mask + o * 256u + i);
        const float4* cp = reinterpret_cast<const float4*>(coeffs + ((size_t)(o * 256u + i)) * 64u + kg * 8u);
        float4 c0 = __ldg(cp), c1 = __ldg(cp + 1);
        __half2 t0 = __floats2half2_rn(c0.x * mv, c0.y * mv), t1 = __floats2half2_rn(c0.z * mv, c0.w * mv);
        __half2 t2 = __floats2half2_rn(c1.x * mv, c1.y * mv), t3 = __floats2half2_rn(c1.z * mv, c1.w * mv);
        uint32_t bo = o * 128u + kg * 16u, sw = bo ^ ((bo >> 3) & 0x70u);
        uint4 v;
        v.x = *reinterpret_cast<uint32_t*>(&t0);
        v.y = *reinterpret_cast<uint32_t*>(&t1);
        v.z = *reinterpret_cast<uint32_t*>(&t2);
        v.w = *reinterpret_cast<uint32_t*>(&t3);
        *reinterpret_cast<uint4*>(reinterpret_cast<char*>(g_Cs) + (size_t)i * 32768u + sw) = v;
    } else {
        int b = blockIdx.x - 2048, i = threadIdx.x;
        float u = __ldg(x + (size_t)b * D_IN + i);
        float Nv[4]; int k0 = 0;
        uint4 rec = {0u, 0u, 0u, 0u};
        if (basis4c(u, Nv, k0)) {
            __half2 w01 = __floats2half2_rn(Nv[0], Nv[1]);
            __half2 w23 = __floats2half2_rn(Nv[2], Nv[3]);
            rec.x = *reinterpret_cast<uint32_t*>(&w01);
            rec.y = *reinterpret_cast<uint32_t*>(&w23);
            rec.z = (uint32_t)(k0 * 2);
        }
        g_W[(size_t)b * D_IN + i] = rec;
    }
}

// tcgen05 GEMM: M-paired, K=64/stage, 3 stages, CTA-local pipeline, D0/D1-interleaved dispatch
__global__ void __launch_bounds__(192, 1)
kan_gemm_tc(const float* __restrict__ x) {
#if HAS_TC
    extern __shared__ char smem[];
    uint32_t sb = smem_u32(smem);
    int tid = threadIdx.x, wid = tid >> 5;
    int mp = blockIdx.x & 15;     // M-pair: rows [mp*256, mp*256+256)
    int kc = blockIdx.x >> 4;     // K chunk 0..7

    if (tid == 0) {
        #pragma unroll
        for (int s = 0; s < STAGES; s++) {
            mbar_init(sb + SM_FULL + 8 * s, 5);   // 4 producer-warp arrives + expect_tx
            mbar_init(sb + SM_DONE + 8 * s, 1);   // local MMA commit
        }
        mbar_init(sb + SM_FINAL, 1);
    }
    if (wid == 5) {
        asm volatile("tcgen05.alloc.cta_group::1.sync.aligned.shared::cta.b32 [%0], %1;"
                     :: "r"(sb + SM_TMEM), "r"(512u) : "memory");
        asm volatile("tcgen05.relinquish_alloc_permit.cta_group::1.sync.aligned;");
    }
    // zero all A stages once
    for (uint32_t off = tid * 16u; off < (uint32_t)(STAGES * A_ST); off += 192u * 16u)
        sts128_zero(sb + SM_A + off);
    __syncthreads();

    uint32_t tmem;
    asm volatile("ld.shared.b32 %0, [%1];" : "=r"(tmem) : "r"(sb + SM_TMEM));

    if (tid < 128) {
        // ---- A producer: 2 records/stage; clear-all-then-write-all; warp-aggregated arrive ----
        const uint4* recs0 = g_W + ((size_t)(mp * 256 + tid)) * D_IN + kc * I_PER;
        const uint4* recs1 = g_W + ((size_t)(mp * 256 + 128 + tid)) * D_IN + kc * I_PER;
        uint32_t trow = (uint32_t)tid * 128u;
        uint32_t off_old[STAGES][2] = {{0, 0}, {0, 0}, {0, 0}};
        uint4 r0n = recs0[0], r1n = recs1[0];
        int st = 0, q = 0;
        for (int it = 0; it < ITERS; it++) {
            uint4 r0 = r0n, r1 = r1n;
            if (it + 1 < ITERS) { r0n = recs0[it + 1]; r1n = recs1[it + 1]; }
            mbar_wait(sb + SM_DONE + 8 * st, (uint32_t)((q - 1) & 1));
            uint32_t base0 = sb + SM_A + (uint32_t)st * A_ST;
            uint32_t base1 = base0 + 16384u;
            // phase 1: clear ALL stale entries
            #pragma unroll
            for (int j = 0; j < 4; j++) {
                uint32_t bo0 = trow + off_old[st][0] + 2u * j;
                sts_u16(base0 + (bo0 ^ ((bo0 >> 3) & 0x70u)), 0);
                uint32_t bo1 = trow + off_old[st][1] + 2u * j;
                sts_u16(base1 + (bo1 ^ ((bo1 >> 3) & 0x70u)), 0);
            }
            // phase 2: write ALL new entries
            uint16_t w0[4] = { (uint16_t)(r0.x & 0xffff), (uint16_t)(r0.x >> 16),
                               (uint16_t)(r0.y & 0xffff), (uint16_t)(r0.y >> 16) };
            uint16_t w1[4] = { (uint16_t)(r1.x & 0xffff), (uint16_t)(r1.x >> 16),
                               (uint16_t)(r1.y & 0xffff), (uint16_t)(r1.y >> 16) };
            #pragma unroll
            for (int j = 0; j < 4; j++) {
                uint32_t bn0 = trow + r0.z + 2u * j;
                sts_u16(base0 + (bn0 ^ ((bn0 >> 3) & 0x70u)), w0[j]);
                uint32_t bn1 = trow + r1.z + 2u * j;
                sts_u16(base1 + (bn1 ^ ((bn1 >> 3) & 0x70u)), w1[j]);
            }
            off_old[st][0] = r0.z;
            off_old[st][1] = r1.z;
            __syncwarp();
            if (elect_one()) mbar_arrive(sb + SM_FULL + 8 * st);
            if (++st == STAGES) { st = 0; q++; }
        }
    } else if (tid == 128) {
        // ---- B producer: unicast 32KB bulk copy per stage ----
        const char* src0 = reinterpret_cast<const char*>(g_Cs) + (size_t)(kc * I_PER) * 32768u;
        int st = 0, q = 0;
        for (int it = 0; it < ITERS; it++) {
            mbar_wait_rlx(sb + SM_DONE + 8 * st, (uint32_t)((q - 1) & 1));
            mbar_expect_tx(sb + SM_FULL + 8 * st, B_ST);
            asm volatile(
                "cp.async.bulk.shared::cluster.global.mbarrier::complete_tx::bytes [%0], [%1], %2, [%3];"
                :: "r"(sb + SM_B + st * B_ST), "l"(src0 + (size_t)it * 32768u),
                   "r"((uint32_t)B_ST), "r"(sb + SM_FULL + 8 * st) : "memory");
            if (++st == STAGES) { st = 0; q++; }
        }
    } else if (wid == 5) {
        // ---- MMA warp: D0/D1-INTERLEAVED dispatches (independent accumulators back-to-back) ----
        int st = 0, q = 0;
        for (int it = 0; it < ITERS; it++) {
            mbar_wait(sb + SM_FULL + 8 * st, (uint32_t)(q & 1));   // acquire
            fence_async_shared();                                    // generic->async for A stores
            if (elect_one()) {
                uint64_t da = DESC_BASE | (((uint64_t)((sb + SM_A + st * A_ST) >> 4)) & 0x3FFF);
                uint64_t db = DESC_BASE | (((uint64_t)((sb + SM_B + st * B_ST) >> 4)) & 0x3FFF);
                #pragma unroll
                for (int ks = 0; ks < 4; ks++) {
                    uint32_t en = (it == 0 && ks == 0) ? 0u : 1u;
                    #pragma unroll
                    for (int hm = 0; hm < 2; hm++) {
                        asm volatile(
                            "{ .reg .pred p; setp.ne.u32 p, %4, 0;"
                            " tcgen05.mma.cta_group::1.kind::f16 [%0], %1, %2, %3, {%5,%5,%5,%5}, p; }"
                            :: "r"(tmem + hm * 256),
                               "l"(da + hm * 1024 + 2 * ks),
                               "l"(db + 2 * ks),
                               "r"(MMA_IDESC), "r"(en), "r"(0u) : "memory");
                    }
                }
                asm volatile("tcgen05.commit.cta_group::1.mbarrier::arrive::one.shared::cluster.b64 [%0];"
                             :: "r"(sb + SM_DONE + 8 * st) : "memory");
            }
            if (++st == STAGES) { st = 0; q++; }
        }
        if (elect_one())
            asm volatile("tcgen05.commit.cta_group::1.mbarrier::arrive::one.shared::cluster.b64 [%0];"
                         :: "r"(sb + SM_FINAL) : "memory");
    }
    __syncthreads();

    if (tid < 128) {
        mbar_wait(sb + SM_FINAL, 0);
        asm volatile("tcgen05.fence::after_thread_sync;" ::: "memory");
        float* base = g_partial + (size_t)kc * (B_DIM * D_OUT);
        #pragma unroll
        for (int hm = 0; hm < 2; hm++) {
            float* dst = base + (size_t)(mp * 256 + hm * 128 + tid) * D_OUT;
            #pragma unroll
            for (int c = 0; c < NT; c += 32) {
                uint32_t r[32];
                asm volatile(
                    "tcgen05.ld.sync.aligned.32x32b.x32.b32 "
                    "{%0,%1,%2,%3,%4,%5,%6,%7,%8,%9,%10,%11,%12,%13,%14,%15,"
                    "%16,%17,%18,%19,%20,%21,%22,%23,%24,%25,%26,%27,%28,%29,%30,%31}, [%32];"
                    : "=r"(r[0]), "=r"(r[1]), "=r"(r[2]), "=r"(r[3]), "=r"(r[4]), "=r"(r[5]),
                      "=r"(r[6]), "=r"(r[7]), "=r"(r[8]), "=r"(r[9]), "=r"(r[10]), "=r"(r[11]),
                      "=r"(r[12]), "=r"(r[13]), "=r"(r[14]), "=r"(r[15]), "=r"(r[16]), "=r"(r[17]),
                      "=r"(r[18]), "=r"(r[19]), "=r"(r[20]), "=r"(r[21]), "=r"(r[22]), "=r"(r[23]),
                      "=r"(r[24]), "=r"(r[25]), "=r"(r[26]), "=r"(r[27]), "=r"(r[28]), "=r"(r[29]),
                      "=r"(r[30]), "=r"(r[31])
                    : "r"(tmem + hm * 256 + c));
                asm volatile("tcgen05.wait::ld.sync.aligned;" ::: "memory");
                #pragma unroll
                for (int j = 0; j < 32; j += 4) {
                    float4 v;
                    v.x = __uint_as_float(r[j]); v.y = __uint_as_float(r[j + 1]);
                    v.z = __uint_as_float(r[j + 2]); v.w = __uint_as_float(r[j + 3]);
                    *reinterpret_cast<float4*>(dst + c + j) = v;
                }
            }
        }
    }
    __syncthreads();
    if (wid == 5)
        asm volatile("tcgen05.dealloc.cta_group::1.sync.aligned.b32 %0, %1;" :: "r"(tmem), "r"(512u));
#else
    (void)x;
#endif
}

__global__ void __launch_bounds__(256) kan_reduce(float* __restrict__ out) {
    uint32_t idx = blockIdx.x * 256u + threadIdx.x;
    const float4* p = reinterpret_cast<const float4*>(g_partial);
    float4 r = p[idx];
    #pragma unroll
    for (int s = 1; s < KSPLIT; s++) {
        float4 v = p[idx + (size_t)s * 262144u];
        r.x += v.x; r.y += v.y; r.z += v.z; r.w += v.w;
    }
    reinterpret_cast<float4*>(out)[idx] = r;
}

extern "C" void kernel_launch(void* const* d_in, const int* in_sizes, int n_in,
                              void* d_out, int out_size) {
    const float* x = (const float*)d_in[0];
    const float* coeffs = (const float*)d_in[1];
    const float* mask = (const float*)d_in[2];
    float* out = (float*)d_out;
    (void)in_sizes; (void)n_in; (void)out_size;

    cudaFuncSetAttribute(kan_gemm_tc, cudaFuncAttributeMaxDynamicSharedMemorySize, SMEM_TC);

    kan_prep<<<6144, 256>>>(coeffs, mask, x);
    kan_gemm_tc<<<128, 192, SMEM_TC>>>(x);
    kan_reduce<<<1024, 256>>>(out);
}

// round 14
// speedup vs baseline: 3.8627x; 1.2098x over previous
#include <cuda_runtime.h>
#include <cuda_fp16.h>
#include <cstdint>

#define DEV __device__ __forceinline__

#if defined(__CUDA_ARCH_FEAT_SM103_ALL) || defined(__CUDA_ARCH_FAMILY_SPECIFIC__) || \
    (defined(__CUDA_ARCH_SPECIFIC__) && (__CUDA_ARCH_SPECIFIC__ == 1030))
#define HAS_TC 1
#else
#define HAS_TC 0
#endif

static constexpr int B_DIM = 4096, D_IN = 256, D_OUT = 256, KBAS = 64;
static constexpr int KSPLIT = 8, I_PER = D_IN / KSPLIT;   // 32 i per CTA
static constexpr int MT = 128, NT = 256;
static constexpr int STAGES = 3;
static constexpr int ITERS = I_PER;       // 32

static constexpr uint32_t MMA_IDESC = (1u << 4) | ((NT / 8) << 17) | ((MT / 16) << 24);
static constexpr uint64_t DESC_BASE =
    (uint64_t(2) << 61) | (uint64_t(1) << 46) | (uint64_t(64) << 32) | (uint64_t(1) << 16);

__device__ __half g_Cs[(size_t)D_IN * D_OUT * KBAS];          // SW128 fp16 B tiles (8MB)
__device__ __half g_partial[(size_t)KSPLIT * B_DIM * D_OUT];  // fp16 partials (16MB)

// tc smem layout (CTA-local barriers)
static constexpr int SM_TMEM = 0, SM_FULL = 16, SM_DONE = 48, SM_FINAL = 80;
static constexpr int A_ST = 2 * MT * KBAS * 2;                 // 32768 (two M=128 subtiles)
static constexpr int B_ST = NT * KBAS * 2;                     // 32768
static constexpr int SM_A = 1024;
static constexpr int SM_B = SM_A + STAGES * A_ST;              // 99328
static constexpr int SMEM_TC = SM_B + STAGES * B_ST;           // 197632

DEV uint32_t smem_u32(const void* p) {
    uint32_t a;
    asm("{ .reg .u64 t; cvta.to.shared.u64 t, %1; cvt.u32.u64 %0, t; }" : "=r"(a) : "l"(p));
    return a;
}
DEV uint32_t elect_one() {
    uint32_t r;
    asm volatile("{ .reg .pred p; elect.sync _|p, 0xFFFFFFFF; selp.b32 %0,1,0,p; }" : "=r"(r));
    return r;
}
DEV void mbar_init(uint32_t m, uint32_t c) {
    asm volatile("mbarrier.init.shared.b64 [%0], %1;" :: "r"(m), "r"(c) : "memory");
}
DEV void mbar_arrive(uint32_t m) {
    asm volatile("mbarrier.arrive.release.cta.shared::cta.b64 _, [%0];" :: "r"(m) : "memory");
}
DEV void mbar_expect_tx(uint32_t m, uint32_t b) {
    asm volatile("mbarrier.arrive.expect_tx.shared.b64 _, [%0], %1;" :: "r"(m), "r"(b) : "memory");
}
DEV void mbar_wait(uint32_t m, uint32_t ph) {   // acquire
    uint32_t done;
    asm volatile("{ .reg .pred p; mbarrier.try_wait.parity.acquire.cta.shared::cta.b64 p, [%1], %2;"
                 " selp.b32 %0,1,0,p; }" : "=r"(done) : "r"(m), "r"(ph) : "memory");
    while (!done)
        asm volatile("{ .reg .pred p; mbarrier.try_wait.parity.acquire.cta.shared::cta.b64 p, [%1], %2, 0x989680;"
                     " selp.b32 %0,1,0,p; }" : "=r"(done) : "r"(m), "r"(ph) : "memory");
}
DEV void mbar_wait_rlx(uint32_t m, uint32_t ph) {
    uint32_t done;
    asm volatile("{ .reg .pred p; mbarrier.try_wait.parity.relaxed.cta.shared::cta.b64 p, [%1], %2, 0x989680;"
                 " selp.b32 %0,1,0,p; }" : "=r"(done) : "r"(m), "r"(ph) : "memory");
    while (!done)
        asm volatile("{ .reg .pred p; mbarrier.try_wait.parity.relaxed.cta.shared::cta.b64 p, [%1], %2, 0x989680;"
                     " selp.b32 %0,1,0,p; }" : "=r"(done) : "r"(m), "r"(ph) : "memory");
}
DEV void fence_async_shared() { asm volatile("fence.proxy.async.shared::cta;" ::: "memory"); }
DEV void sts128_zero(uint32_t a) {
    asm volatile("st.shared.v4.b32 [%0], {%1,%1,%1,%1};" :: "r"(a), "r"(0u) : "memory");
}
DEV void sts_u16(uint32_t a, uint16_t v) {
    asm volatile("st.shared.u16 [%0], %1;" :: "r"(a), "h"(v) : "memory");
}

// exact basis via cardinal cubic polynomials on uniform knots (== Cox-de Boor here).
DEV bool basis4c(float u, float Nv[4], int& k0) {
    if (!(u >= -4.0f && u < 4.0f)) return false;
    const float h = 8.0f / 67.0f, i1 = 8.375f;
    int s = (int)((u + 4.0f) * i1);
    s = min(max(s, 0), 66);
    float ts = fmaf((float)s, h, -4.0f);
    if (u < ts) s--;
    else if (u >= ts + h) s++;
    s = min(max(s, 0), 66);
    ts = fmaf((float)s, h, -4.0f);
    k0 = min(max(s - 3, 0), 60);
    float r = (u - ts) * i1;
    float r2 = r * r, r3 = r2 * r;
    float q0 = r3 * (1.0f / 6.0f);
    float q1 = fmaf(-3.0f, r3, fmaf(3.0f, r2, fmaf(3.0f, r, 1.0f))) * (1.0f / 6.0f);
    float q2 = fmaf(3.0f, r3, fmaf(-6.0f, r2, 4.0f)) * (1.0f / 6.0f);
    float omr = 1.0f - r;
    float q3 = omr * omr * omr * (1.0f / 6.0f);
    int dd = s - k0;
    #pragma unroll
    for (int j = 0; j < 4; j++) {
        int d = dd - j;
        Nv[j] = (d == 0) ? q0 : (d == 1) ? q1 : (d == 2) ? q2 : (d == 3) ? q3 : 0.0f;
    }
    return true;
}

// produce 4 fp16 weight bits + byte offset for one x value
DEV void basis_rec(float u, uint16_t w[4], uint32_t& z) {
    float Nv[4]; int k0 = 0;
    w[0] = w[1] = w[2] = w[3] = 0; z = 0;
    if (basis4c(u, Nv, k0)) {
        #pragma unroll
        for (int j = 0; j < 4; j++) w[j] = __half_as_ushort(__float2half_rn(Nv[j]));
        z = (uint32_t)(k0 * 2);
    }
}

// prep: convert coeffs*mask -> SW128 fp16 tiles (basis now lives in the GEMM producers)
__global__ void __launch_bounds__(256) kan_prep(const float* __restrict__ coeffs,
                                                const float* __restrict__ mask) {
    uint32_t idx = blockIdx.x * 256u + threadIdx.x;
    uint32_t i = idx >> 11, o = (idx >> 3) & 255u, kg = idx & 7u;
    float mv = __ldg(mask + o * 256u + i);
    const float4* cp = reinterpret_cast<const float4*>(coeffs + ((size_t)(o * 256u + i)) * 64u + kg * 8u);
    float4 c0 = __ldg(cp), c1 = __ldg(cp + 1);
    __half2 t0 = __floats2half2_rn(c0.x * mv, c0.y * mv), t1 = __floats2half2_rn(c0.z * mv, c0.w * mv);
    __half2 t2 = __floats2half2_rn(c1.x * mv, c1.y * mv), t3 = __floats2half2_rn(c1.z * mv, c1.w * mv);
    uint32_t bo = o * 128u + kg * 16u, sw = bo ^ ((bo >> 3) & 0x70u);
    uint4 v;
    v.x = *reinterpret_cast<uint32_t*>(&t0);
    v.y = *reinterpret_cast<uint32_t*>(&t1);
    v.z = *reinterpret_cast<uint32_t*>(&t2);
    v.w = *reinterpret_cast<uint32_t*>(&t3);
    *reinterpret_cast<uint4*>(reinterpret_cast<char*>(g_Cs) + (size_t)i * 32768u + sw) = v;
}

// tcgen05 GEMM: M-paired, K=64/stage, 3 stages, basis computed inline in A-producers
__global__ void __launch_bounds__(192, 1)
kan_gemm_tc(const float* __restrict__ x) {
#if HAS_TC
    extern __shared__ char smem[];
    uint32_t sb = smem_u32(smem);
    int tid = threadIdx.x, wid = tid >> 5;
    int mp = blockIdx.x & 15;     // M-pair: rows [mp*256, mp*256+256)
    int kc = blockIdx.x >> 4;     // K chunk 0..7

    if (tid == 0) {
        #pragma unroll
        for (int s = 0; s < STAGES; s++) {
            mbar_init(sb + SM_FULL + 8 * s, 5);   // 4 producer-warp arrives + expect_tx
            mbar_init(sb + SM_DONE + 8 * s, 1);
        }
        mbar_init(sb + SM_FINAL, 1);
    }
    if (wid == 5) {
        asm volatile("tcgen05.alloc.cta_group::1.sync.aligned.shared::cta.b32 [%0], %1;"
                     :: "r"(sb + SM_TMEM), "r"(512u) : "memory");
        asm volatile("tcgen05.relinquish_alloc_permit.cta_group::1.sync.aligned;");
    }
    for (uint32_t off = tid * 16u; off < (uint32_t)(STAGES * A_ST); off += 192u * 16u)
        sts128_zero(sb + SM_A + off);
    __syncthreads();

    uint32_t tmem;
    asm volatile("ld.shared.b32 %0, [%1];" : "=r"(tmem) : "r"(sb + SM_TMEM));

    if (tid < 128) {
        // ---- A producer: inline basis from x; clear-all-then-write-all ----
        const float* x0 = x + (size_t)(mp * 256 + tid) * D_IN + kc * I_PER;
        const float* x1 = x0 + (size_t)128 * D_IN;
        uint32_t trow = (uint32_t)tid * 128u;
        uint32_t off_old[STAGES][2] = {{0, 0}, {0, 0}, {0, 0}};
        float u0n = __ldg(x0), u1n = __ldg(x1);
        int st = 0, q = 0;
        for (int it = 0; it < ITERS; it++) {
            float u0 = u0n, u1 = u1n;
            if (it + 1 < ITERS) { u0n = __ldg(x0 + it + 1); u1n = __ldg(x1 + it + 1); }
            uint16_t w0[4], w1[4];
            uint32_t z0, z1;
            basis_rec(u0, w0, z0);
            basis_rec(u1, w1, z1);
            mbar_wait(sb + SM_DONE + 8 * st, (uint32_t)((q - 1) & 1));
            uint32_t base0 = sb + SM_A + (uint32_t)st * A_ST;
            uint32_t base1 = base0 + 16384u;
            #pragma unroll
            for (int j = 0; j < 4; j++) {
                uint32_t bo0 = trow + off_old[st][0] + 2u * j;
                sts_u16(base0 + (bo0 ^ ((bo0 >> 3) & 0x70u)), 0);
                uint32_t bo1 = trow + off_old[st][1] + 2u * j;
                sts_u16(base1 + (bo1 ^ ((bo1 >> 3) & 0x70u)), 0);
            }
            #pragma unroll
            for (int j = 0; j < 4; j++) {
                uint32_t bn0 = trow + z0 + 2u * j;
                sts_u16(base0 + (bn0 ^ ((bn0 >> 3) & 0x70u)), w0[j]);
                uint32_t bn1 = trow + z1 + 2u * j;
                sts_u16(base1 + (bn1 ^ ((bn1 >> 3) & 0x70u)), w1[j]);
            }
            off_old[st][0] = z0;
            off_old[st][1] = z1;
            __syncwarp();
            if (elect_one()) mbar_arrive(sb + SM_FULL + 8 * st);
            if (++st == STAGES) { st = 0; q++; }
        }
    } else if (tid == 128) {
        // ---- B producer: unicast 32KB bulk copy per stage ----
        const char* src0 = reinterpret_cast<const char*>(g_Cs) + (size_t)(kc * I_PER) * 32768u;
        int st = 0, q = 0;
        for (int it = 0; it < ITERS; it++) {
            mbar_wait_rlx(sb + SM_DONE + 8 * st, (uint32_t)((q - 1) & 1));
            mbar_expect_tx(sb + SM_FULL + 8 * st, B_ST);
            asm volatile(
                "cp.async.bulk.shared::cluster.global.mbarrier::complete_tx::bytes [%0], [%1], %2, [%3];"
                :: "r"(sb + SM_B + st * B_ST), "l"(src0 + (size_t)it * 32768u),
                   "r"((uint32_t)B_ST), "r"(sb + SM_FULL + 8 * st) : "memory");
            if (++st == STAGES) { st = 0; q++; }
        }
    } else if (wid == 5) {
        // ---- MMA warp ----
        int st = 0, q = 0;
        for (int it = 0; it < ITERS; it++) {
            mbar_wait(sb + SM_FULL + 8 * st, (uint32_t)(q & 1));
            fence_async_shared();
            if (elect_one()) {
                uint64_t da = DESC_BASE | (((uint64_t)((sb + SM_A + st * A_ST) >> 4)) & 0x3FFF);
                uint64_t db = DESC_BASE | (((uint64_t)((sb + SM_B + st * B_ST) >> 4)) & 0x3FFF);
                #pragma unroll
                for (int ks = 0; ks < 4; ks++) {
                    uint32_t en = (it == 0 && ks == 0) ? 0u : 1u;
                    #pragma unroll
                    for (int hm = 0; hm < 2; hm++) {
                        asm volatile(
                            "{ .reg .pred p; setp.ne.u32 p, %4, 0;"
                            " tcgen05.mma.cta_group::1.kind::f16 [%0], %1, %2, %3, {%5,%5,%5,%5}, p; }"
                            :: "r"(tmem + hm * 256),
                               "l"(da + hm * 1024 + 2 * ks),
                               "l"(db + 2 * ks),
                               "r"(MMA_IDESC), "r"(en), "r"(0u) : "memory");
                    }
                }
                asm volatile("tcgen05.commit.cta_group::1.mbarrier::arrive::one.shared::cluster.b64 [%0];"
                             :: "r"(sb + SM_DONE + 8 * st) : "memory");
            }
            if (++st == STAGES) { st = 0; q++; }
        }
        if (elect_one())
            asm volatile("tcgen05.commit.cta_group::1.mbarrier::arrive::one.shared::cluster.b64 [%0];"
                         :: "r"(sb + SM_FINAL) : "memory");
    }
    __syncthreads();

    if (tid < 128) {
        mbar_wait(sb + SM_FINAL, 0);
        asm volatile("tcgen05.fence::after_thread_sync;" ::: "memory");
        __half* base = g_partial + (size_t)kc * (B_DIM * D_OUT);
        #pragma unroll
        for (int hm = 0; hm < 2; hm++) {
            __half* dst = base + (size_t)(mp * 256 + hm * 128 + tid) * D_OUT;
            #pragma unroll
            for (int c = 0; c < NT; c += 32) {
                uint32_t r[32];
                asm volatile(
                    "tcgen05.ld.sync.aligned.32x32b.x32.b32 "
                    "{%0,%1,%2,%3,%4,%5,%6,%7,%8,%9,%10,%11,%12,%13,%14,%15,"
                    "%16,%17,%18,%19,%20,%21,%22,%23,%24,%25,%26,%27,%28,%29,%30,%31}, [%32];"
                    : "=r"(r[0]), "=r"(r[1]), "=r"(r[2]), "=r"(r[3]), "=r"(r[4]), "=r"(r[5]),
                      "=r"(r[6]), "=r"(r[7]), "=r"(r[8]), "=r"(r[9]), "=r"(r[10]), "=r"(r[11]),
                      "=r"(r[12]), "=r"(r[13]), "=r"(r[14]), "=r"(r[15]), "=r"(r[16]), "=r"(r[17]),
                      "=r"(r[18]), "=r"(r[19]), "=r"(r[20]), "=r"(r[21]), "=r"(r[22]), "=r"(r[23]),
                      "=r"(r[24]), "=r"(r[25]), "=r"(r[26]), "=r"(r[27]), "=r"(r[28]), "=r"(r[29]),
                      "=r"(r[30]), "=r"(r[31])
                    : "r"(tmem + hm * 256 + c));
                asm volatile("tcgen05.wait::ld.sync.aligned;" ::: "memory");
                uint32_t h[16];
                #pragma unroll
                for (int j = 0; j < 16; j++) {
                    __half2 p2 = __floats2half2_rn(__uint_as_float(r[2 * j]),
                                                   __uint_as_float(r[2 * j + 1]));
                    h[j] = *reinterpret_cast<uint32_t*>(&p2);
                }
                #pragma unroll
                for (int v = 0; v < 4; v++) {
                    uint4 st4;
                    st4.x = h[v * 4 + 0]; st4.y = h[v * 4 + 1];
                    st4.z = h[v * 4 + 2]; st4.w = h[v * 4 + 3];
                    *reinterpret_cast<uint4*>(dst + c + v * 8) = st4;
                }
            }
        }
    }
    __syncthreads();
    if (wid == 5)
        asm volatile("tcgen05.dealloc.cta_group::1.sync.aligned.b32 %0, %1;" :: "r"(tmem), "r"(512u));
#else
    (void)x;
#endif
}

// reduce: sum 8 fp16 partial slices -> fp32 out
__global__ void __launch_bounds__(256) kan_reduce(float* __restrict__ out) {
    uint32_t idx = blockIdx.x * 256u + threadIdx.x;       // 131072 threads, 8 outputs each
    const uint4* p = reinterpret_cast<const uint4*>(g_partial);
    float acc[8] = {0, 0, 0, 0, 0, 0, 0, 0};
    #pragma unroll
    for (int s = 0; s < KSPLIT; s++) {
        uint4 v = p[idx + (uint32_t)s * 131072u];
        const __half2* h = reinterpret_cast<const __half2*>(&v);
        #pragma unroll
        for (int j = 0; j < 4; j++) {
            float2 f = __half22float2(h[j]);
            acc[2 * j] += f.x;
            acc[2 * j + 1] += f.y;
        }
    }
    float4* o = reinterpret_cast<float4*>(out + (size_t)idx * 8);
    o[0] = make_float4(acc[0], acc[1], acc[2], acc[3]);
    o[1] = make_float4(acc[4], acc[5], acc[6], acc[7]);
}

extern "C" void kernel_launch(void* const* d_in, const int* in_sizes, int n_in,
                              void* d_out, int out_size) {
    const float* x = (const float*)d_in[0];
    const float* coeffs = (const float*)d_in[1];
    const float* mask = (const float*)d_in[2];
    float* out = (float*)d_out;
    (void)in_sizes; (void)n_in; (void)out_size;

    cudaFuncSetAttribute(kan_gemm_tc, cudaFuncAttributeMaxDynamicSharedMemorySize, SMEM_TC);

    kan_prep<<<2048, 256>>>(coeffs, mask);
    kan_gemm_tc<<<128, 192, SMEM_TC>>>(x);
    kan_reduce<<<512, 256>>>(out);
}